// round 2
// baseline (speedup 1.0000x reference)
#include <cuda_runtime.h>

#define BS    8
#define CIN   128
#define NSTK  32
#define NPNT  128
#define CU    256      // 2*CIN: channels entering each GCN
#define COUT  256
#define NDN   4096     // NSTK*NPNT
#define KDN   10
#define ISQ   0.9999950000374997f   // 1/sqrt(1+1e-5)
#define NEG_INF (-1e30f)

// f32x2 packed-FMA helpers (sm_100+): 2 fp32 FMAs per issue slot
#define FMA2(c,a,b)   asm("fma.rn.f32x2 %0, %1, %2, %0;" : "+l"(c) : "l"(a), "l"(b))
#define DUP2(d,s)     asm("mov.b64 %0, {%1, %1};"        : "=l"(d) : "f"(s))
#define UNPK2(lo,hi,c) asm("mov.b64 {%0, %1}, %2;" : "=f"(lo), "=f"(hi) : "l"(c))

// ---------------- scratch (device globals; no runtime allocation) ----------
__device__ float g_sp_in[BS*CU*NSTK];
__device__ float g_xT[(size_t)BS*NDN*CU];          // [b][n][c] point features, row-major
__device__ float g_xx[BS*NDN];                     // squared norms
__device__ float g_dist[(size_t)BS*NDN*NDN];       // neg_dist (536 MB)
__device__ int   g_idx[BS*NDN*KDN];
__device__ float g_ynb[(size_t)BS*NDN*COUT];       // W1 @ x
__device__ float g_yct[(size_t)BS*NDN*COUT];       // (W2-W1) @ x + b
__device__ float g_udn[(size_t)BS*NDN*COUT];       // GCN output, [b][n][o]

// ---------------- 1) sparse input: concat(sparse, max_p dense) -------------
__global__ void k_build_sp_in(const float* __restrict__ sp, const float* __restrict__ dn){
    int e = blockIdx.x*blockDim.x + threadIdx.x;   // 65536 threads
    int b = e >> 13; int r = e & 8191; int c = r >> 5; int s = r & 31;
    float v;
    if (c < CIN) {
        v = sp[(b*CIN + c)*NSTK + s];
    } else {
        const float* p = dn + (((size_t)(b*CIN + (c-CIN))*NSTK + s)*NPNT);
        v = NEG_INF;
        #pragma unroll 8
        for (int i = 0; i < NPNT; i++) v = fmaxf(v, p[i]);
    }
    g_sp_in[e] = v;
}

// ---------------- 2) sparse GCN (N=32, k=2), writes u_sp to d_out ----------
__global__ void k_sparse_gcn(const float* __restrict__ W, const float* __restrict__ bias,
                             const float* __restrict__ gam, const float* __restrict__ bet,
                             float* __restrict__ out){
    int b = blockIdx.x; int oc = blockIdx.y; int tid = threadIdx.x;
    __shared__ float xs[CU*NSTK];       // [c][s]
    __shared__ float xx[NSTK];
    __shared__ float nd[NSTK*NSTK];
    __shared__ int   i1s[NSTK], i2s[NSTK];

    for (int e = tid; e < CU*NSTK; e += 256) xs[e] = g_sp_in[b*CU*NSTK + e];
    __syncthreads();
    if (tid < NSTK){
        float s = 0.f;
        for (int c = 0; c < CU; c++){ float v = xs[c*NSTK+tid]; s += v*v; }
        xx[tid] = s;
    }
    __syncthreads();
    for (int e = tid; e < NSTK*NSTK; e += 256){
        int n = e >> 5, m = e & 31;
        float d = 0.f;
        for (int c = 0; c < CU; c++) d += xs[c*NSTK+n]*xs[c*NSTK+m];
        nd[e] = 2.f*d - xx[n] - xx[m];
    }
    __syncthreads();
    if (tid < NSTK){
        float b1 = NEG_INF, b2 = NEG_INF; int j1 = 0, j2 = 0;
        for (int m = 0; m < NSTK; m++){
            float v = nd[tid*NSTK+m];
            if (v > b1){ b2=b1; j2=j1; b1=v; j1=m; }
            else if (v > b2){ b2=v; j2=m; }
        }
        i1s[tid]=j1; i2s[tid]=j2;
    }
    __syncthreads();

    int o   = oc*32 + (tid >> 3);
    int nb0 = tid & 7;
    float a1[4]={0,0,0,0}, a2[4]={0,0,0,0}, ac[4]={0,0,0,0};
    int j1[4], j2[4];
    #pragma unroll
    for (int u=0;u<4;u++){ int n = nb0 + u*8; j1[u]=i1s[n]; j2[u]=i2s[n]; }
    const float* wr = W + o*(2*CU);
    for (int c = 0; c < CU; c++){
        float w1 = wr[c];
        float wd = wr[CU + c] - w1;
        const float* xc = xs + c*NSTK;
        #pragma unroll
        for (int u=0;u<4;u++){
            int n = nb0 + u*8;
            a1[u] += w1*xc[j1[u]];
            a2[u] += w1*xc[j2[u]];
            ac[u] += wd*xc[n];
        }
    }
    float bo = bias[o], go = gam[o]*ISQ, beo = bet[o];
    #pragma unroll
    for (int u=0;u<4;u++){
        int n = nb0 + u*8;
        float h1 = go*(a1[u]+ac[u]+bo) + beo; h1 = fmaxf(h1, 0.f);
        float h2 = go*(a2[u]+ac[u]+bo) + beo; h2 = fmaxf(h2, 0.f);
        out[(b*COUT + o)*NSTK + n] = fmaxf(h1, h2);
    }
}

// ---------------- 3) dense point features, transposed [b][n][c] ------------
__global__ void k_build_xT(const float* __restrict__ sp, const float* __restrict__ dn){
    int s = blockIdx.x, b = blockIdx.y, tid = threadIdx.x;
    __shared__ float sm[128*65];
    __shared__ float sps[CIN];
    size_t rowbase = (size_t)b*NDN + (size_t)s*NPNT;
    for (int cc0 = 0; cc0 < CIN; cc0 += 64){
        #pragma unroll
        for (int j = 0; j < 32; j++){
            int e = j*256 + tid; int p = e & 127; int ci = e >> 7;
            sm[p*65 + ci] = dn[(((size_t)(b*CIN + cc0 + ci)*NSTK + s)*NPNT) + p];
        }
        __syncthreads();
        #pragma unroll
        for (int j = 0; j < 32; j++){
            int e = j*256 + tid; int ci = e & 63; int p = e >> 6;
            g_xT[(rowbase + p)*CU + cc0 + ci] = sm[p*65 + ci];
        }
        __syncthreads();
    }
    if (tid < CIN) sps[tid] = sp[(b*CIN + tid)*NSTK + s];
    __syncthreads();
    #pragma unroll
    for (int j = 0; j < 64; j++){
        int e = j*256 + tid; int c = e & 127; int p = e >> 7;
        g_xT[(rowbase + p)*CU + CIN + c] = sps[c];
    }
}

// ---------------- 4) squared norms ----------------------------------------
__global__ void k_xx(){
    int w = (blockIdx.x * blockDim.x + threadIdx.x) >> 5;
    int lane = threadIdx.x & 31;
    const float* r = g_xT + (size_t)w*CU;
    float s = 0.f;
    #pragma unroll
    for (int j = 0; j < CU; j += 32){ float v = r[j+lane]; s += v*v; }
    #pragma unroll
    for (int off=16; off; off>>=1) s += __shfl_down_sync(0xffffffffu, s, off);
    if (lane == 0) g_xx[w] = s;
}

// ============================================================================
// f32x2 GEMM engine: block tile 128(q) x 256(m), K-chunk 16, 256 threads,
// microtile 8 x 16 (= 8 x 8 f32x2 pairs). Register-prefetch double buffering.
// ============================================================================
#define QT 128
#define MT 256
#define KC 16

// ---------------- 5) y_nb / y_ct GEMMs: [4096,256] @ W[256,256]^T ----------
__global__ void __launch_bounds__(256) k_wgemm(const float* __restrict__ W,
                                               const float* __restrict__ bias){
    int z = blockIdx.z; int b = z >> 1, var = z & 1;
    int q0 = blockIdx.y*QT;
    const float* A = g_xT + (size_t)b*NDN*CU;
    float* C = (var ? g_yct : g_ynb) + (size_t)b*NDN*COUT;
    __shared__ __align__(16) float As[KC][QT];
    __shared__ __align__(16) float Bs[KC][MT];
    int tid = threadIdx.x; int tx = tid & 15, ty = tid >> 4;

    // prefetch chunk 0
    float4 pa[2], pb[4];
    #pragma unroll
    for (int s = 0; s < 2; s++){
        int f = tid + s*256; int row = f >> 2, kq = (f & 3)*4;
        pa[s] = *(const float4*)(A + (size_t)(q0+row)*CU + kq);
    }
    #pragma unroll
    for (int s = 0; s < 4; s++){
        int f = tid + s*256; int n = f >> 2, kq = (f & 3)*4;
        float4 w1 = *(const float4*)(W + n*(2*CU) + kq);
        if (var){
            float4 w2 = *(const float4*)(W + n*(2*CU) + CU + kq);
            w1 = make_float4(w2.x-w1.x, w2.y-w1.y, w2.z-w1.z, w2.w-w1.w);
        }
        pb[s] = w1;
    }

    unsigned long long acc[8][8];
    #pragma unroll
    for (int i=0;i<8;i++)
        #pragma unroll
        for (int j=0;j<8;j++) acc[i][j] = 0ull;

    for (int kt = 0; kt < CU; kt += KC){
        // commit prefetched chunk to smem
        #pragma unroll
        for (int s = 0; s < 2; s++){
            int f = tid + s*256; int row = f >> 2, kq = (f & 3)*4;
            As[kq+0][row]=pa[s].x; As[kq+1][row]=pa[s].y;
            As[kq+2][row]=pa[s].z; As[kq+3][row]=pa[s].w;
        }
        #pragma unroll
        for (int s = 0; s < 4; s++){
            int f = tid + s*256; int n = f >> 2, kq = (f & 3)*4;
            Bs[kq+0][n]=pb[s].x; Bs[kq+1][n]=pb[s].y;
            Bs[kq+2][n]=pb[s].z; Bs[kq+3][n]=pb[s].w;
        }
        __syncthreads();
        // prefetch next chunk
        if (kt + KC < CU){
            int ktn = kt + KC;
            #pragma unroll
            for (int s = 0; s < 2; s++){
                int f = tid + s*256; int row = f >> 2, kq = (f & 3)*4;
                pa[s] = *(const float4*)(A + (size_t)(q0+row)*CU + ktn + kq);
            }
            #pragma unroll
            for (int s = 0; s < 4; s++){
                int f = tid + s*256; int n = f >> 2, kq = (f & 3)*4;
                float4 w1 = *(const float4*)(W + n*(2*CU) + ktn + kq);
                if (var){
                    float4 w2 = *(const float4*)(W + n*(2*CU) + CU + ktn + kq);
                    w1 = make_float4(w2.x-w1.x, w2.y-w1.y, w2.z-w1.z, w2.w-w1.w);
                }
                pb[s] = w1;
            }
        }
        #pragma unroll
        for (int kk = 0; kk < KC; kk++){
            float4 a0 = *(const float4*)&As[kk][ty*8];
            float4 a1 = *(const float4*)&As[kk][ty*8+4];
            unsigned long long ad[8];
            DUP2(ad[0], a0.x); DUP2(ad[1], a0.y); DUP2(ad[2], a0.z); DUP2(ad[3], a0.w);
            DUP2(ad[4], a1.x); DUP2(ad[5], a1.y); DUP2(ad[6], a1.z); DUP2(ad[7], a1.w);
            ulonglong2 b0 = *(const ulonglong2*)&Bs[kk][tx*16];
            ulonglong2 b1 = *(const ulonglong2*)&Bs[kk][tx*16+4];
            ulonglong2 b2 = *(const ulonglong2*)&Bs[kk][tx*16+8];
            ulonglong2 b3 = *(const ulonglong2*)&Bs[kk][tx*16+12];
            unsigned long long bp[8] = {b0.x,b0.y,b1.x,b1.y,b2.x,b2.y,b3.x,b3.y};
            #pragma unroll
            for (int i=0;i<8;i++)
                #pragma unroll
                for (int j=0;j<8;j++) FMA2(acc[i][j], ad[i], bp[j]);
        }
        __syncthreads();
    }

    float bj[16];
    #pragma unroll
    for (int j=0;j<16;j++) bj[j] = var ? bias[tx*16+j] : 0.f;
    #pragma unroll
    for (int i=0;i<8;i++){
        float o[16];
        #pragma unroll
        for (int j=0;j<8;j++){
            float lo, hi; UNPK2(lo, hi, acc[i][j]);
            o[2*j] = lo + bj[2*j]; o[2*j+1] = hi + bj[2*j+1];
        }
        float* cr = C + (size_t)(q0 + ty*8 + i)*COUT + tx*16;
        #pragma unroll
        for (int q=0;q<4;q++)
            *(float4*)(cr + q*4) = make_float4(o[4*q],o[4*q+1],o[4*q+2],o[4*q+3]);
    }
}

// ---------------- 6) neg_dist = 2*x.x^T - xx_q - xx_m (the big one) --------
__global__ void __launch_bounds__(256) k_dist(){
    int b = blockIdx.z;
    int q0 = blockIdx.y*QT, m0 = blockIdx.x*MT;
    const float* A = g_xT + (size_t)b*NDN*CU;
    __shared__ __align__(16) float As[KC][QT];
    __shared__ __align__(16) float Bs[KC][MT];
    int tid = threadIdx.x; int tx = tid & 15, ty = tid >> 4;

    float4 pa[2], pb[4];
    #pragma unroll
    for (int s = 0; s < 2; s++){
        int f = tid + s*256; int row = f >> 2, kq = (f & 3)*4;
        pa[s] = *(const float4*)(A + (size_t)(q0+row)*CU + kq);
    }
    #pragma unroll
    for (int s = 0; s < 4; s++){
        int f = tid + s*256; int row = f >> 2, kq = (f & 3)*4;
        pb[s] = *(const float4*)(A + (size_t)(m0+row)*CU + kq);
    }

    unsigned long long acc[8][8];
    #pragma unroll
    for (int i=0;i<8;i++)
        #pragma unroll
        for (int j=0;j<8;j++) acc[i][j] = 0ull;

    for (int kt = 0; kt < CU; kt += KC){
        #pragma unroll
        for (int s = 0; s < 2; s++){
            int f = tid + s*256; int row = f >> 2, kq = (f & 3)*4;
            As[kq+0][row]=pa[s].x; As[kq+1][row]=pa[s].y;
            As[kq+2][row]=pa[s].z; As[kq+3][row]=pa[s].w;
        }
        #pragma unroll
        for (int s = 0; s < 4; s++){
            int f = tid + s*256; int row = f >> 2, kq = (f & 3)*4;
            Bs[kq+0][row]=pb[s].x; Bs[kq+1][row]=pb[s].y;
            Bs[kq+2][row]=pb[s].z; Bs[kq+3][row]=pb[s].w;
        }
        __syncthreads();
        if (kt + KC < CU){
            int ktn = kt + KC;
            #pragma unroll
            for (int s = 0; s < 2; s++){
                int f = tid + s*256; int row = f >> 2, kq = (f & 3)*4;
                pa[s] = *(const float4*)(A + (size_t)(q0+row)*CU + ktn + kq);
            }
            #pragma unroll
            for (int s = 0; s < 4; s++){
                int f = tid + s*256; int row = f >> 2, kq = (f & 3)*4;
                pb[s] = *(const float4*)(A + (size_t)(m0+row)*CU + ktn + kq);
            }
        }
        #pragma unroll
        for (int kk = 0; kk < KC; kk++){
            float4 a0 = *(const float4*)&As[kk][ty*8];
            float4 a1 = *(const float4*)&As[kk][ty*8+4];
            unsigned long long ad[8];
            DUP2(ad[0], a0.x); DUP2(ad[1], a0.y); DUP2(ad[2], a0.z); DUP2(ad[3], a0.w);
            DUP2(ad[4], a1.x); DUP2(ad[5], a1.y); DUP2(ad[6], a1.z); DUP2(ad[7], a1.w);
            ulonglong2 b0 = *(const ulonglong2*)&Bs[kk][tx*16];
            ulonglong2 b1 = *(const ulonglong2*)&Bs[kk][tx*16+4];
            ulonglong2 b2 = *(const ulonglong2*)&Bs[kk][tx*16+8];
            ulonglong2 b3 = *(const ulonglong2*)&Bs[kk][tx*16+12];
            unsigned long long bp[8] = {b0.x,b0.y,b1.x,b1.y,b2.x,b2.y,b3.x,b3.y};
            #pragma unroll
            for (int i=0;i<8;i++)
                #pragma unroll
                for (int j=0;j<8;j++) FMA2(acc[i][j], ad[i], bp[j]);
        }
        __syncthreads();
    }

    float xq[8], xm[16];
    #pragma unroll
    for (int i=0;i<8;i++) xq[i] = g_xx[b*NDN + q0 + ty*8 + i];
    #pragma unroll
    for (int j=0;j<16;j++) xm[j] = g_xx[b*NDN + m0 + tx*16 + j];
    #pragma unroll
    for (int i=0;i<8;i++){
        float o[16];
        #pragma unroll
        for (int j=0;j<8;j++){
            float lo, hi; UNPK2(lo, hi, acc[i][j]);
            o[2*j]   = 2.f*lo - xq[i] - xm[2*j];
            o[2*j+1] = 2.f*hi - xq[i] - xm[2*j+1];
        }
        float* dr = g_dist + (size_t)(b*NDN + q0 + ty*8 + i)*NDN + m0 + tx*16;
        #pragma unroll
        for (int q=0;q<4;q++)
            *(float4*)(dr + q*4) = make_float4(o[4*q],o[4*q+1],o[4*q+2],o[4*q+3]);
    }
}

// ---------------- 7) streaming top-10 per row (stable, ties -> low index) --
__global__ void k_topk(){
    int warp = threadIdx.x >> 5, lane = threadIdx.x & 31;
    int row = blockIdx.x*4 + warp;                 // 0..32767
    const float4* r4 = (const float4*)(g_dist + (size_t)row*NDN);
    float v[10]; int ix[10];
    #pragma unroll
    for (int j=0;j<10;j++){ v[j]=NEG_INF; ix[j]=0x7fffffff; }
    for (int it = 0; it < NDN/128; it++){
        float4 f = r4[it*32 + lane];
        int mb = (it*32 + lane)*4;
        float vals[4] = {f.x, f.y, f.z, f.w};
        #pragma unroll
        for (int j=0;j<4;j++){
            float val = vals[j];
            if (val > v[9]){
                v[9]=val; ix[9]=mb+j;
                #pragma unroll
                for (int t=9;t>0;t--){
                    if (v[t] > v[t-1]){
                        float tv=v[t]; v[t]=v[t-1]; v[t-1]=tv;
                        int ti=ix[t]; ix[t]=ix[t-1]; ix[t-1]=ti;
                    }
                }
            }
        }
    }
    int* out = g_idx + row*KDN;
    #pragma unroll
    for (int r = 0; r < KDN; r++){
        float cv = v[0]; int ci = ix[0];
        #pragma unroll
        for (int off=16; off; off>>=1){
            float ov = __shfl_down_sync(0xffffffffu, cv, off);
            int   oi = __shfl_down_sync(0xffffffffu, ci, off);
            if (ov > cv || (ov == cv && oi < ci)){ cv=ov; ci=oi; }
        }
        ci = __shfl_sync(0xffffffffu, ci, 0);
        if (ci == ix[0]){
            #pragma unroll
            for (int t=0;t<9;t++){ v[t]=v[t+1]; ix[t]=ix[t+1]; }
            v[9]=NEG_INF; ix[9]=0x7fffffff;
        }
        if (lane == 0) out[r] = ci;
    }
}

// ---------------- 8) gather + BN + relu + max over k -----------------------
__global__ void k_assemble(const float* __restrict__ gam, const float* __restrict__ bet){
    int n = blockIdx.x, b = blockIdx.y, o = threadIdx.x;
    __shared__ int ids[KDN];
    if (o < KDN) ids[o] = g_idx[((size_t)b*NDN + n)*KDN + o];
    __syncthreads();
    size_t base = (size_t)b*NDN;
    float ct  = g_yct[(base + n)*COUT + o];
    float go  = gam[o]*ISQ, beo = bet[o];
    float vmax = NEG_INF;
    #pragma unroll
    for (int k = 0; k < KDN; k++){
        float h = ct + g_ynb[(base + ids[k])*COUT + o];
        h = go*h + beo;
        h = fmaxf(h, 0.f);
        vmax = fmaxf(vmax, h);
    }
    g_udn[(base + n)*COUT + o] = vmax;
}

// ---------------- 9) conv (1x3, stride 2, pad 1) + BN + relu ---------------
__global__ void k_conv(const float* __restrict__ Wc, const float* __restrict__ bc,
                       const float* __restrict__ gc, const float* __restrict__ bec,
                       float* __restrict__ yout){
    int s = blockIdx.x, b = blockIdx.y, o = threadIdx.x;
    __shared__ float sm[64][133];   // [i-chunk][p+1], rows 0 & 129 zero padding
    float acc[64];
    #pragma unroll
    for (int q=0;q<64;q++) acc[q]=0.f;
    size_t nbase = (size_t)b*NDN + (size_t)s*NPNT;
    for (int ic = 0; ic < 4; ic++){
        #pragma unroll
        for (int j = 0; j < 32; j++){
            int e = j*256 + o; int i = e & 63; int p = e >> 6;
            sm[i][p+1] = g_udn[(nbase + p)*COUT + ic*64 + i];
        }
        if (o < 64){ sm[o][0]=0.f; sm[o][129]=0.f; }
        __syncthreads();
        const float* wr = Wc + o*(COUT*3) + ic*64*3;
        for (int i = 0; i < 64; i++){
            float w0=wr[i*3], w1=wr[i*3+1], w2=wr[i*3+2];
            float xa = sm[i][0];
            #pragma unroll
            for (int q=0;q<64;q++){
                float xb = sm[i][2*q+1];
                float xc = sm[i][2*q+2];
                acc[q] += w0*xa;
                acc[q] += w1*xb;
                acc[q] += w2*xc;
                xa = xc;
            }
        }
        __syncthreads();
    }
    float bo=bc[o], go=gc[o]*ISQ, beo=bec[o];
    float* yo = yout + (((size_t)b*COUT + o)*NSTK + s)*64;
    #pragma unroll
    for (int q=0;q<64;q++){
        float v = go*(acc[q]+bo) + beo;
        yo[q] = fmaxf(v, 0.f);
    }
}

// ---------------- launch ----------------------------------------------------
extern "C" void kernel_launch(void* const* d_in, const int* in_sizes, int n_in,
                              void* d_out, int out_size){
    const float* sp    = (const float*)d_in[0];
    const float* dn    = (const float*)d_in[1];
    const float* W_sp  = (const float*)d_in[2];
    const float* b_sp  = (const float*)d_in[3];
    const float* gsp   = (const float*)d_in[4];
    const float* besp  = (const float*)d_in[5];
    const float* W_dn  = (const float*)d_in[6];
    const float* b_dn  = (const float*)d_in[7];
    const float* gdn   = (const float*)d_in[8];
    const float* bedn  = (const float*)d_in[9];
    const float* W_c   = (const float*)d_in[10];
    const float* b_c   = (const float*)d_in[11];
    const float* g_c   = (const float*)d_in[12];
    const float* be_c  = (const float*)d_in[13];
    float* out = (float*)d_out;

    k_build_sp_in<<<256, 256>>>(sp, dn);
    k_sparse_gcn <<<dim3(8,8), 256>>>(W_sp, b_sp, gsp, besp, out);
    k_build_xT   <<<dim3(NSTK, BS), 256>>>(sp, dn);
    k_xx         <<<4096, 256>>>();
    k_wgemm      <<<dim3(1, 32, 16), 256>>>(W_dn, b_dn);
    k_dist       <<<dim3(16, 32, 8), 256>>>();
    k_topk       <<<8192, 128>>>();
    k_assemble   <<<dim3(NDN, BS), 256>>>(gdn, bedn);
    k_conv       <<<dim3(NSTK, BS), 256>>>(W_c, b_c, g_c, be_c, out + BS*COUT*NSTK);
}

// round 5
// speedup vs baseline: 1.6910x; 1.6910x over previous
#include <cuda_runtime.h>

#define BS    8
#define CIN   128
#define NSTK  32
#define NPNT  128
#define CU    256      // 2*CIN: channels entering each GCN
#define COUT  256
#define NDN   4096     // NSTK*NPNT
#define KDN   10
#define NCAND 16
#define ISQ   0.9999950000374997f   // 1/sqrt(1+1e-5)
#define NEG_INF (-1e30f)

// ---------------- scratch (device globals; no runtime allocation) ----------
__device__ __align__(256) float g_sp_in[BS*CU*NSTK];
__device__ __align__(256) float g_xT [(size_t)BS*NDN*CU];   // exact fp32 [b][n][c]
__device__ __align__(256) float g_xhi[(size_t)BS*NDN*CU];   // tf32-rounded
__device__ __align__(256) float g_xlo[(size_t)BS*NDN*CU];   // residual (tf32-rounded)
__device__ __align__(256) float g_xx[BS*NDN];               // exact squared norms
__device__ __align__(256) float g_dist[(size_t)BS*NDN*NDN]; // approx neg_dist (536 MB)
__device__ __align__(256) int   g_idx16[(size_t)BS*NDN*NCAND];
__device__ __align__(256) int   g_idx[BS*NDN*KDN];
__device__ __align__(256) float g_Wh[2][COUT*CU];           // [0]=W1 hi, [1]=(W2-W1) hi
__device__ __align__(256) float g_Wl[2][COUT*CU];
__device__ __align__(256) float g_ynb[(size_t)BS*NDN*COUT];
__device__ __align__(256) float g_yct[(size_t)BS*NDN*COUT];
__device__ __align__(256) float g_udn[(size_t)BS*NDN*COUT];

// ---------------- PTX helpers ----------------------------------------------
__device__ __forceinline__ unsigned f2tf(float x){
    unsigned u; asm("cvt.rna.tf32.f32 %0, %1;" : "=r"(u) : "f"(x)); return u;
}
__device__ __forceinline__ void mma8(float* c, const unsigned* a, const unsigned* b){
    asm volatile("mma.sync.aligned.m16n8k8.row.col.f32.tf32.tf32.f32 "
        "{%0,%1,%2,%3}, {%4,%5,%6,%7}, {%8,%9}, {%0,%1,%2,%3};"
        : "+f"(c[0]),"+f"(c[1]),"+f"(c[2]),"+f"(c[3])
        : "r"(a[0]),"r"(a[1]),"r"(a[2]),"r"(a[3]), "r"(b[0]),"r"(b[1]));
}
__device__ __forceinline__ void cp16(unsigned dst, const void* src){
    asm volatile("cp.async.ca.shared.global [%0], [%1], 16;" :: "r"(dst), "l"(src));
}
#define CPCOMMIT() asm volatile("cp.async.commit_group;")
#define CPWAIT1()  asm volatile("cp.async.wait_group 1;")
#define CPWAIT0()  asm volatile("cp.async.wait_group 0;")

// ---------------- 1) sparse input: concat(sparse, max_p dense) -------------
__global__ void k_build_sp_in(const float* __restrict__ sp, const float* __restrict__ dn){
    int e = blockIdx.x*blockDim.x + threadIdx.x;
    int b = e >> 13; int r = e & 8191; int c = r >> 5; int s = r & 31;
    float v;
    if (c < CIN) {
        v = sp[(b*CIN + c)*NSTK + s];
    } else {
        const float* p = dn + (((size_t)(b*CIN + (c-CIN))*NSTK + s)*NPNT);
        v = NEG_INF;
        #pragma unroll 8
        for (int i = 0; i < NPNT; i++) v = fmaxf(v, p[i]);
    }
    g_sp_in[e] = v;
}

// ---------------- 2) sparse GCN (N=32, k=2), writes u_sp to d_out ----------
__global__ void k_sparse_gcn(const float* __restrict__ W, const float* __restrict__ bias,
                             const float* __restrict__ gam, const float* __restrict__ bet,
                             float* __restrict__ out){
    int b = blockIdx.x; int oc = blockIdx.y; int tid = threadIdx.x;
    __shared__ float xs[CU*NSTK];
    __shared__ float xx[NSTK];
    __shared__ float nd[NSTK*NSTK];
    __shared__ int   i1s[NSTK], i2s[NSTK];

    for (int e = tid; e < CU*NSTK; e += 256) xs[e] = g_sp_in[b*CU*NSTK + e];
    __syncthreads();
    if (tid < NSTK){
        float s = 0.f;
        for (int c = 0; c < CU; c++){ float v = xs[c*NSTK+tid]; s += v*v; }
        xx[tid] = s;
    }
    __syncthreads();
    for (int e = tid; e < NSTK*NSTK; e += 256){
        int n = e >> 5, m = e & 31;
        float d = 0.f;
        for (int c = 0; c < CU; c++) d += xs[c*NSTK+n]*xs[c*NSTK+m];
        nd[e] = 2.f*d - xx[n] - xx[m];
    }
    __syncthreads();
    if (tid < NSTK){
        float b1 = NEG_INF, b2 = NEG_INF; int j1 = 0, j2 = 0;
        for (int m = 0; m < NSTK; m++){
            float v = nd[tid*NSTK+m];
            if (v > b1){ b2=b1; j2=j1; b1=v; j1=m; }
            else if (v > b2){ b2=v; j2=m; }
        }
        i1s[tid]=j1; i2s[tid]=j2;
    }
    __syncthreads();

    int o   = oc*32 + (tid >> 3);
    int nb0 = tid & 7;
    float a1[4]={0,0,0,0}, a2[4]={0,0,0,0}, ac[4]={0,0,0,0};
    int j1[4], j2[4];
    #pragma unroll
    for (int u=0;u<4;u++){ int n = nb0 + u*8; j1[u]=i1s[n]; j2[u]=i2s[n]; }
    const float* wr = W + o*(2*CU);
    for (int c = 0; c < CU; c++){
        float w1 = wr[c];
        float wd = wr[CU + c] - w1;
        const float* xc = xs + c*NSTK;
        #pragma unroll
        for (int u=0;u<4;u++){
            int n = nb0 + u*8;
            a1[u] += w1*xc[j1[u]];
            a2[u] += w1*xc[j2[u]];
            ac[u] += wd*xc[n];
        }
    }
    float bo = bias[o], go = gam[o]*ISQ, beo = bet[o];
    #pragma unroll
    for (int u=0;u<4;u++){
        int n = nb0 + u*8;
        float h1 = go*(a1[u]+ac[u]+bo) + beo; h1 = fmaxf(h1, 0.f);
        float h2 = go*(a2[u]+ac[u]+bo) + beo; h2 = fmaxf(h2, 0.f);
        out[(b*COUT + o)*NSTK + n] = fmaxf(h1, h2);
    }
}

// ---------------- 3) dense point features, transposed [b][n][c] ------------
__global__ void k_build_xT(const float* __restrict__ sp, const float* __restrict__ dn){
    int s = blockIdx.x, b = blockIdx.y, tid = threadIdx.x;
    __shared__ float sm[128*65];
    __shared__ float sps[CIN];
    size_t rowbase = (size_t)b*NDN + (size_t)s*NPNT;
    for (int cc0 = 0; cc0 < CIN; cc0 += 64){
        #pragma unroll
        for (int j = 0; j < 32; j++){
            int e = j*256 + tid; int p = e & 127; int ci = e >> 7;
            sm[p*65 + ci] = dn[(((size_t)(b*CIN + cc0 + ci)*NSTK + s)*NPNT) + p];
        }
        __syncthreads();
        #pragma unroll
        for (int j = 0; j < 32; j++){
            int e = j*256 + tid; int ci = e & 63; int p = e >> 6;
            g_xT[(rowbase + p)*CU + cc0 + ci] = sm[p*65 + ci];
        }
        __syncthreads();
    }
    if (tid < CIN) sps[tid] = sp[(b*CIN + tid)*NSTK + s];
    __syncthreads();
    #pragma unroll
    for (int j = 0; j < 64; j++){
        int e = j*256 + tid; int c = e & 127; int p = e >> 7;
        g_xT[(rowbase + p)*CU + CIN + c] = sps[c];
    }
}

// ---------------- 3b) tf32 hi/lo split of x --------------------------------
__global__ void k_cvt_x(){
    size_t e = (size_t)blockIdx.x*256 + threadIdx.x;
    float x = g_xT[e];
    unsigned h = f2tf(x);
    float hf = __uint_as_float(h);
    float lo = x - hf;
    g_xhi[e] = hf;
    g_xlo[e] = __uint_as_float(f2tf(lo));
}

// ---------------- 3c) tf32 hi/lo split of W1 and (W2-W1) -------------------
__global__ void k_prepw(const float* __restrict__ W){
    int e = blockIdx.x*256 + threadIdx.x;
    int o = e >> 8, c = e & 255;
    float w1 = W[o*(2*CU) + c];
    float wd = W[o*(2*CU) + CU + c] - w1;
    unsigned h1 = f2tf(w1); float l1 = w1 - __uint_as_float(h1);
    unsigned hd = f2tf(wd); float ld = wd - __uint_as_float(hd);
    g_Wh[0][e] = __uint_as_float(h1); g_Wl[0][e] = __uint_as_float(f2tf(l1));
    g_Wh[1][e] = __uint_as_float(hd); g_Wl[1][e] = __uint_as_float(f2tf(ld));
}

// ---------------- 4) squared norms (exact fp32) ----------------------------
__global__ void k_xx(){
    int w = (blockIdx.x * blockDim.x + threadIdx.x) >> 5;
    int lane = threadIdx.x & 31;
    const float* r = g_xT + (size_t)w*CU;
    float s = 0.f;
    #pragma unroll
    for (int j = 0; j < CU; j += 32){ float v = r[j+lane]; s += v*v; }
    #pragma unroll
    for (int off=16; off; off>>=1) s += __shfl_down_sync(0xffffffffu, s, off);
    if (lane == 0) g_xx[w] = s;
}

// ============================================================================
// tf32 mma GEMM engines. Block 128x128, 8 warps @ m64n32, k-chunk 16,
// smem rows padded to 20 floats, cp.async double buffering.
// ============================================================================
#define LDW 20
#define TSZ (128*LDW)

// ---------------- 5) y_nb / y_ct: 3xtf32 (hi*hi + hi*lo + lo*hi) -----------
__global__ void __launch_bounds__(256) k_wgemm_mma(const float* __restrict__ bias){
    extern __shared__ float smw[];
    const int tid = threadIdx.x;
    const int z = blockIdx.z; const int b = z >> 1, var = z & 1;
    const int q0 = blockIdx.y*128, n0 = blockIdx.x*128;
    const float* Ahg = g_xhi + (size_t)b*NDN*CU;
    const float* Alg = g_xlo + (size_t)b*NDN*CU;
    const float* Bhg = g_Wh[var];
    const float* Blg = g_Wl[var];
    float* C = (var ? g_yct : g_ynb) + (size_t)b*NDN*COUT;

    float* tAh[2] = { smw,          smw + TSZ   };
    float* tAl[2] = { smw + 2*TSZ,  smw + 3*TSZ };
    float* tBh[2] = { smw + 4*TSZ,  smw + 5*TSZ };
    float* tBl[2] = { smw + 6*TSZ,  smw + 7*TSZ };
    unsigned ub = (unsigned)__cvta_generic_to_shared(smw);
    unsigned uAh[2] = { ub,            ub + TSZ*4   };
    unsigned uAl[2] = { ub + 2*TSZ*4,  ub + 3*TSZ*4 };
    unsigned uBh[2] = { ub + 4*TSZ*4,  ub + 5*TSZ*4 };
    unsigned uBl[2] = { ub + 6*TSZ*4,  ub + 7*TSZ*4 };

    const int lane = tid & 31, w = tid >> 5;
    const int wm = w & 1, wn = w >> 1;
    const int gid = lane >> 2, t4 = lane & 3;
    const int srow = tid >> 2, scc = (tid & 3)*4;

    float acc[4][4][4];
    #pragma unroll
    for (int i=0;i<4;i++)
        #pragma unroll
        for (int j=0;j<4;j++)
            #pragma unroll
            for (int r=0;r<4;r++) acc[i][j][r]=0.f;

#define STAGE_W(bi, kt) do { \
    cp16(uAh[bi]+(srow*LDW+scc)*4,      Ahg + (size_t)(q0+srow)*CU + (kt) + scc); \
    cp16(uAh[bi]+((srow+64)*LDW+scc)*4, Ahg + (size_t)(q0+srow+64)*CU + (kt) + scc); \
    cp16(uAl[bi]+(srow*LDW+scc)*4,      Alg + (size_t)(q0+srow)*CU + (kt) + scc); \
    cp16(uAl[bi]+((srow+64)*LDW+scc)*4, Alg + (size_t)(q0+srow+64)*CU + (kt) + scc); \
    cp16(uBh[bi]+(srow*LDW+scc)*4,      Bhg + (size_t)(n0+srow)*CU + (kt) + scc); \
    cp16(uBh[bi]+((srow+64)*LDW+scc)*4, Bhg + (size_t)(n0+srow+64)*CU + (kt) + scc); \
    cp16(uBl[bi]+(srow*LDW+scc)*4,      Blg + (size_t)(n0+srow)*CU + (kt) + scc); \
    cp16(uBl[bi]+((srow+64)*LDW+scc)*4, Blg + (size_t)(n0+srow+64)*CU + (kt) + scc); \
    CPCOMMIT(); \
} while(0)

    STAGE_W(0, 0);
    for (int it = 0; it < 16; it++){
        if (it < 15){ STAGE_W((it+1)&1, (it+1)*16); CPWAIT1(); }
        else CPWAIT0();
        __syncthreads();
        const int bi = it & 1;
        const float* Ah = tAh[bi]; const float* Al = tAl[bi];
        const float* Bh = tBh[bi]; const float* Bl = tBl[bi];
        #pragma unroll
        for (int ks = 0; ks < 2; ks++){
            const int kk = ks*8;
            unsigned ah[4][4], al[4][4], bh[4][2], bl[4][2];
            #pragma unroll
            for (int mi=0;mi<4;mi++){
                const float* p = Ah + (wm*64+mi*16+gid)*LDW + kk + t4;
                ah[mi][0]=__float_as_uint(p[0]);       ah[mi][1]=__float_as_uint(p[8*LDW]);
                ah[mi][2]=__float_as_uint(p[4]);       ah[mi][3]=__float_as_uint(p[8*LDW+4]);
                const float* q = Al + (wm*64+mi*16+gid)*LDW + kk + t4;
                al[mi][0]=__float_as_uint(q[0]);       al[mi][1]=__float_as_uint(q[8*LDW]);
                al[mi][2]=__float_as_uint(q[4]);       al[mi][3]=__float_as_uint(q[8*LDW+4]);
            }
            #pragma unroll
            for (int ni=0;ni<4;ni++){
                const float* p = Bh + (wn*32+ni*8+gid)*LDW + kk + t4;
                bh[ni][0]=__float_as_uint(p[0]);       bh[ni][1]=__float_as_uint(p[4]);
                const float* q = Bl + (wn*32+ni*8+gid)*LDW + kk + t4;
                bl[ni][0]=__float_as_uint(q[0]);       bl[ni][1]=__float_as_uint(q[4]);
            }
            #pragma unroll
            for (int mi=0;mi<4;mi++)
                #pragma unroll
                for (int ni=0;ni<4;ni++){
                    mma8(acc[mi][ni], ah[mi], bh[ni]);
                    mma8(acc[mi][ni], ah[mi], bl[ni]);
                    mma8(acc[mi][ni], al[mi], bh[ni]);
                }
        }
        __syncthreads();
    }

    #pragma unroll
    for (int mi=0;mi<4;mi++){
        int r0g = q0 + wm*64 + mi*16 + gid;
        #pragma unroll
        for (int ni=0;ni<4;ni++){
            int col = n0 + wn*32 + ni*8 + 2*t4;
            float b0v = var ? bias[col]   : 0.f;
            float b1v = var ? bias[col+1] : 0.f;
            *(float2*)(C + (size_t)r0g*COUT + col)
                = make_float2(acc[mi][ni][0]+b0v, acc[mi][ni][1]+b1v);
            *(float2*)(C + (size_t)(r0g+8)*COUT + col)
                = make_float2(acc[mi][ni][2]+b0v, acc[mi][ni][3]+b1v);
        }
    }
#undef STAGE_W
}

// ---------------- 6) approx neg_dist (1-pass tf32) -------------------------
__global__ void __launch_bounds__(256) k_dist_mma(){
    extern __shared__ float smd[];
    const int tid = threadIdx.x;
    const int b = blockIdx.z;
    const int q0 = blockIdx.y*128, m0 = blockIdx.x*128;
    const float* A = g_xhi + (size_t)b*NDN*CU;

    float* tA[2] = { smd,          smd + TSZ   };
    float* tB[2] = { smd + 2*TSZ,  smd + 3*TSZ };
    unsigned ub = (unsigned)__cvta_generic_to_shared(smd);
    unsigned uA[2] = { ub,           ub + TSZ*4   };
    unsigned uB[2] = { ub + 2*TSZ*4, ub + 3*TSZ*4 };

    const int lane = tid & 31, w = tid >> 5;
    const int wm = w & 1, wn = w >> 1;
    const int gid = lane >> 2, t4 = lane & 3;
    const int srow = tid >> 2, scc = (tid & 3)*4;

    float acc[4][4][4];
    #pragma unroll
    for (int i=0;i<4;i++)
        #pragma unroll
        for (int j=0;j<4;j++)
            #pragma unroll
            for (int r=0;r<4;r++) acc[i][j][r]=0.f;

#define STAGE_D(bi, kt) do { \
    cp16(uA[bi]+(srow*LDW+scc)*4,      A + (size_t)(q0+srow)*CU + (kt) + scc); \
    cp16(uA[bi]+((srow+64)*LDW+scc)*4, A + (size_t)(q0+srow+64)*CU + (kt) + scc); \
    cp16(uB[bi]+(srow*LDW+scc)*4,      A + (size_t)(m0+srow)*CU + (kt) + scc); \
    cp16(uB[bi]+((srow+64)*LDW+scc)*4, A + (size_t)(m0+srow+64)*CU + (kt) + scc); \
    CPCOMMIT(); \
} while(0)

    STAGE_D(0, 0);
    for (int it = 0; it < 16; it++){
        if (it < 15){ STAGE_D((it+1)&1, (it+1)*16); CPWAIT1(); }
        else CPWAIT0();
        __syncthreads();
        const int bi = it & 1;
        const float* Ab = tA[bi]; const float* Bb = tB[bi];
        #pragma unroll
        for (int ks = 0; ks < 2; ks++){
            const int kk = ks*8;
            unsigned af[4][4], bf[4][2];
            #pragma unroll
            for (int mi=0;mi<4;mi++){
                const float* p = Ab + (wm*64+mi*16+gid)*LDW + kk + t4;
                af[mi][0]=__float_as_uint(p[0]);   af[mi][1]=__float_as_uint(p[8*LDW]);
                af[mi][2]=__float_as_uint(p[4]);   af[mi][3]=__float_as_uint(p[8*LDW+4]);
            }
            #pragma unroll
            for (int ni=0;ni<4;ni++){
                const float* p = Bb + (wn*32+ni*8+gid)*LDW + kk + t4;
                bf[ni][0]=__float_as_uint(p[0]);   bf[ni][1]=__float_as_uint(p[4]);
            }
            #pragma unroll
            for (int mi=0;mi<4;mi++)
                #pragma unroll
                for (int ni=0;ni<4;ni++) mma8(acc[mi][ni], af[mi], bf[ni]);
        }
        __syncthreads();
    }

    const float* xxb = g_xx + b*NDN;
    #pragma unroll
    for (int mi=0;mi<4;mi++){
        int r0g = q0 + wm*64 + mi*16 + gid;
        float xq0 = xxb[r0g], xq1 = xxb[r0g+8];
        #pragma unroll
        for (int ni=0;ni<4;ni++){
            int col = m0 + wn*32 + ni*8 + 2*t4;
            float xm0 = xxb[col], xm1 = xxb[col+1];
            *(float2*)(g_dist + (size_t)(b*NDN + r0g)*NDN + col)
                = make_float2(2.f*acc[mi][ni][0] - xq0 - xm0, 2.f*acc[mi][ni][1] - xq0 - xm1);
            *(float2*)(g_dist + (size_t)(b*NDN + r0g + 8)*NDN + col)
                = make_float2(2.f*acc[mi][ni][2] - xq1 - xm0, 2.f*acc[mi][ni][3] - xq1 - xm1);
        }
    }
#undef STAGE_D
}

// ---------------- 7) streaming approx top-16 per row -----------------------
__global__ void k_topk(){
    int warp = threadIdx.x >> 5, lane = threadIdx.x & 31;
    int row = blockIdx.x*4 + warp;
    const float4* r4 = (const float4*)(g_dist + (size_t)row*NDN);
    float v[NCAND]; int ix[NCAND];
    #pragma unroll
    for (int j=0;j<NCAND;j++){ v[j]=NEG_INF; ix[j]=0x7fffffff; }
    for (int it = 0; it < NDN/128; it++){
        float4 f = r4[it*32 + lane];
        int mb = (it*32 + lane)*4;
        float vals[4] = {f.x, f.y, f.z, f.w};
        #pragma unroll
        for (int j=0;j<4;j++){
            float val = vals[j];
            if (val > v[NCAND-1]){
                v[NCAND-1]=val; ix[NCAND-1]=mb+j;
                #pragma unroll
                for (int t=NCAND-1;t>0;t--){
                    if (v[t] > v[t-1]){
                        float tv=v[t]; v[t]=v[t-1]; v[t-1]=tv;
                        int ti=ix[t]; ix[t]=ix[t-1]; ix[t-1]=ti;
                    }
                }
            }
        }
    }
    int* out = g_idx16 + (size_t)row*NCAND;
    #pragma unroll
    for (int r = 0; r < NCAND; r++){
        float cv = v[0]; int ci = ix[0];
        #pragma unroll
        for (int off=16; off; off>>=1){
            float ov = __shfl_down_sync(0xffffffffu, cv, off);
            int   oi = __shfl_down_sync(0xffffffffu, ci, off);
            if (ov > cv || (ov == cv && oi < ci)){ cv=ov; ci=oi; }
        }
        ci = __shfl_sync(0xffffffffu, ci, 0);
        if (ci == ix[0]){
            #pragma unroll
            for (int t=0;t<NCAND-1;t++){ v[t]=v[t+1]; ix[t]=ix[t+1]; }
            v[NCAND-1]=NEG_INF; ix[NCAND-1]=0x7fffffff;
        }
        if (lane == 0) out[r] = ci;
    }
}

// ---------------- 7b) exact fp32 re-rank of 16 candidates -> top-10 --------
__global__ void k_refine(){
    int warp = threadIdx.x >> 5, lane = threadIdx.x & 31;
    int row = blockIdx.x*4 + warp;          // 0..32767
    int b = row >> 12, n = row & 4095;
    const float* X = g_xT + (size_t)b*NDN*CU;
    const float* xxb = g_xx + b*NDN;
    float q[8];
    #pragma unroll
    for (int j=0;j<8;j++) q[j] = X[(size_t)n*CU + j*32 + lane];
    float xxq = xxb[n];
    const int* cand = g_idx16 + (size_t)row*NCAND;
    float vals[NCAND]; int ids[NCAND];
    #pragma unroll
    for (int c=0;c<NCAND;c++){
        int idx = cand[c];
        const float* Y = X + (size_t)idx*CU;
        float s = 0.f;
        #pragma unroll
        for (int j=0;j<8;j++) s += q[j]*Y[j*32 + lane];
        #pragma unroll
        for (int off=16; off; off>>=1) s += __shfl_down_sync(0xffffffffu, s, off);
        vals[c] = 2.f*s - xxq - xxb[idx];
        ids[c] = idx;
    }
    if (lane == 0){
        int* out = g_idx + (size_t)row*KDN;
        #pragma unroll
        for (int r=0;r<KDN;r++){
            int best = r;
            for (int c=r+1;c<NCAND;c++){
                if (vals[c] > vals[best] ||
                    (vals[c] == vals[best] && ids[c] < ids[best])) best = c;
            }
            float tv=vals[r]; vals[r]=vals[best]; vals[best]=tv;
            int ti=ids[r]; ids[r]=ids[best]; ids[best]=ti;
            out[r] = ids[r];
        }
    }
}

// ---------------- 8) gather + BN + relu + max over k -----------------------
__global__ void k_assemble(const float* __restrict__ gam, const float* __restrict__ bet){
    int n = blockIdx.x, b = blockIdx.y, o = threadIdx.x;
    __shared__ int ids[KDN];
    if (o < KDN) ids[o] = g_idx[((size_t)b*NDN + n)*KDN + o];
    __syncthreads();
    size_t base = (size_t)b*NDN;
    float ct  = g_yct[(base + n)*COUT + o];
    float go  = gam[o]*ISQ, beo = bet[o];
    float vmax = NEG_INF;
    #pragma unroll
    for (int k = 0; k < KDN; k++){
        float h = ct + g_ynb[(base + ids[k])*COUT + o];
        h = go*h + beo;
        h = fmaxf(h, 0.f);
        vmax = fmaxf(vmax, h);
    }
    g_udn[(base + n)*COUT + o] = vmax;
}

// ---------------- 9) conv (1x3, stride 2, pad 1) + BN + relu ---------------
__global__ void k_conv(const float* __restrict__ Wc, const float* __restrict__ bc,
                       const float* __restrict__ gc, const float* __restrict__ bec,
                       float* __restrict__ yout){
    int s = blockIdx.x, b = blockIdx.y, o = threadIdx.x;
    __shared__ float sm[64][133];
    float acc[64];
    #pragma unroll
    for (int q=0;q<64;q++) acc[q]=0.f;
    size_t nbase = (size_t)b*NDN + (size_t)s*NPNT;
    for (int ic = 0; ic < 4; ic++){
        #pragma unroll
        for (int j = 0; j < 32; j++){
            int e = j*256 + o; int i = e & 63; int p = e >> 6;
            sm[i][p+1] = g_udn[(nbase + p)*COUT + ic*64 + i];
        }
        if (o < 64){ sm[o][0]=0.f; sm[o][129]=0.f; }
        __syncthreads();
        const float* wr = Wc + o*(COUT*3) + ic*64*3;
        for (int i = 0; i < 64; i++){
            float w0=wr[i*3], w1=wr[i*3+1], w2=wr[i*3+2];
            float xa = sm[i][0];
            #pragma unroll
            for (int q=0;q<64;q++){
                float xb = sm[i][2*q+1];
                float xc = sm[i][2*q+2];
                acc[q] += w0*xa;
                acc[q] += w1*xb;
                acc[q] += w2*xc;
                xa = xc;
            }
        }
        __syncthreads();
    }
    float bo=bc[o], go=gc[o]*ISQ, beo=bec[o];
    float* yo = yout + (((size_t)b*COUT + o)*NSTK + s)*64;
    #pragma unroll
    for (int q=0;q<64;q++){
        float v = go*(acc[q]+bo) + beo;
        yo[q] = fmaxf(v, 0.f);
    }
}

// ---------------- launch ----------------------------------------------------
extern "C" void kernel_launch(void* const* d_in, const int* in_sizes, int n_in,
                              void* d_out, int out_size){
    const float* sp    = (const float*)d_in[0];
    const float* dn    = (const float*)d_in[1];
    const float* W_sp  = (const float*)d_in[2];
    const float* b_sp  = (const float*)d_in[3];
    const float* gsp   = (const float*)d_in[4];
    const float* besp  = (const float*)d_in[5];
    const float* W_dn  = (const float*)d_in[6];
    const float* b_dn  = (const float*)d_in[7];
    const float* gdn   = (const float*)d_in[8];
    const float* bedn  = (const float*)d_in[9];
    const float* W_c   = (const float*)d_in[10];
    const float* b_c   = (const float*)d_in[11];
    const float* g_c   = (const float*)d_in[12];
    const float* be_c  = (const float*)d_in[13];
    float* out = (float*)d_out;

    cudaFuncSetAttribute(k_wgemm_mma, cudaFuncAttributeMaxDynamicSharedMemorySize, 8*TSZ*4);
    cudaFuncSetAttribute(k_dist_mma,  cudaFuncAttributeMaxDynamicSharedMemorySize, 4*TSZ*4);

    k_build_sp_in<<<256, 256>>>(sp, dn);
    k_sparse_gcn <<<dim3(8,8), 256>>>(W_sp, b_sp, gsp, besp, out);
    k_build_xT   <<<dim3(NSTK, BS), 256>>>(sp, dn);
    k_cvt_x      <<<32768, 256>>>();
    k_prepw      <<<256, 256>>>(W_dn);
    k_xx         <<<4096, 256>>>();
    k_wgemm_mma  <<<dim3(2, 32, 16), 256, 8*TSZ*4>>>(b_dn);
    k_dist_mma   <<<dim3(32, 32, 8), 256, 4*TSZ*4>>>();
    k_topk       <<<8192, 128>>>();
    k_refine     <<<8192, 128>>>();
    k_assemble   <<<dim3(NDN, BS), 256>>>(gdn, bedn);
    k_conv       <<<dim3(NSTK, BS), 256>>>(W_c, b_c, g_c, be_c, out + BS*COUT*NSTK);
}